// round 12
// baseline (speedup 1.0000x reference)
#include <cuda_runtime.h>

// CoupledClustersLossV2 — quarter-class CTAs, static unrolled loop, HBM-bound.
// embeddings: [256 cls][2 pos/neg][32 samples][2048] fp32 = 128 MB.
// ||x - a||^2 = ||x||^2 - (x·s)/16 + ||s||^2/1024,  s = sum of 32 pos rows.
//
// Lessons: R10 (1 CTA/class) streams at t_c=0.85us/chunk-slot but eats a
// 1.18x byte-imbalance (2-class SMs). R11 fixed balance with a dynamic
// persistent loop and t_c regressed to 1.05 (alu/index overhead in-loop).
// Here: 1024 CTAs x 4 static chunks (class = bid>>2, D-slice = bid&3).
// The chunk loop is R10's verbatim machinery — fully unrolled, self-visible
// cp.async (each thread copies exactly the SMEM slots it reads -> no tile
// barrier), 3 stages, ONE barrier per chunk (column-sum exchange). New:
// neg rows never touch SMEM (they don't feed the column sum) — direct
// __ldcg float4 loads issued before the wait_group, halving SMEM traffic.
// Per-class combine: 4 static slots + epoch counter (replay-safe), all sums
// fixed-order -> deterministic. Global mean fused via second epoch counter.

#define NCLS     256
#define NS       32
#define DIM      2048
#define CHUNK    128
#define THREADS  256
#define NPART    4
#define NCH      4                    // chunks per CTA (static)
#define GRID     (NCLS * NPART)       // 1024
#define NSTAGE   3
#define TILE_F4  1024                 // pos-only: 32 rows x 32 float4 = 16KB
#define SMEM_BYTES (NSTAGE * TILE_F4 * 16 + 2 * 8 * CHUNK * 4)   // 57344
#define ROW_F4   (DIM / 4)            // 512
#define MARGIN   0.3f

// per-(class, part) row partials: 0=||pos||^2 1=pos·s 2=||neg||^2 3=neg·s
__device__ float        g_scratch[NCLS][NPART][4][NS];
__device__ unsigned int g_done[NCLS];      // epoch counters (never reset)
__device__ float        g_class_loss[NCLS];
__device__ unsigned int g_cls_done;        // epoch counter (never reset)

__device__ __forceinline__ float dot4(float4 a, float4 b) {
    return fmaf(a.x, b.x, fmaf(a.y, b.y, fmaf(a.z, b.z, a.w * b.w)));
}
__device__ __forceinline__ float wsum(float v) {
#pragma unroll
    for (int o = 16; o > 0; o >>= 1) v += __shfl_xor_sync(0xffffffffu, v, o);
    return v;
}
__device__ __forceinline__ void cp_async16(unsigned smem_dst, const float4* gsrc) {
    asm volatile("cp.async.cg.shared.global [%0], [%1], 16;\n"
                 :: "r"(smem_dst), "l"(gsrc));
}

__global__ __launch_bounds__(THREADS, 2)
void ccl_kernel(const float* __restrict__ emb, float* __restrict__ out)
{
    extern __shared__ float4 sh4[];                       // [NSTAGE][TILE_F4] pos tiles
    float* spart = (float*)(sh4 + NSTAGE * TILE_F4);      // [2][8][CHUNK]

    const int bid  = blockIdx.x;
    const int cls  = bid >> 2;
    const int part = bid & 3;
    const int tid  = threadIdx.x;
    const int warp = tid >> 5;
    const int lane = tid & 31;

    // This thread's fixed slots: pos rows warp+8i (i=0..3), f4-column lane.
    const unsigned slot0  = (unsigned)((warp * 32 + lane) * 16);
    const unsigned smbase = (unsigned)__cvta_generic_to_shared(sh4);
    // Quarter base: class block + part*512 columns; + this thread's row/col.
    const float4* gq = (const float4*)emb + ((size_t)cls << 15)   // 2*NS*DIM/4
                       + (part << 7)                              // part*512/4
                       + (size_t)warp * ROW_F4 + lane;

    // Issue pos chunk c (4 x 16B into this thread's own slots) + commit.
    auto issue = [&](int c) {
        const float4*  g  = gq + (c << 5);                // c * CHUNK/4
        const unsigned sb = smbase + (unsigned)(c % NSTAGE) * (TILE_F4 * 16);
#pragma unroll
        for (int i = 0; i < 4; ++i)
            cp_async16(sb + slot0 + i * 4096u, g + (size_t)(i * 8) * ROW_F4);
        asm volatile("cp.async.commit_group;\n" ::);
    };

    issue(0); issue(1); issue(2);

    float pn[4] = {0.f,0.f,0.f,0.f};
    float tp[4] = {0.f,0.f,0.f,0.f};
    float nn[4] = {0.f,0.f,0.f,0.f};
    float tn[4] = {0.f,0.f,0.f,0.f};

#pragma unroll
    for (int c = 0; c < NCH; ++c) {
        const int sb = c & 1;
        const float4* tile = sh4 + (c % NSTAGE) * TILE_F4;

        // Neg rows bypass SMEM entirely: issue LDGs BEFORE the wait so their
        // latency hides under it. .cg: streaming, no L1 pollution.
        float4 n[4];
#pragma unroll
        for (int i = 0; i < 4; ++i)
            n[i] = __ldcg(gq + (c << 5) + (size_t)(NS + i * 8) * ROW_F4);

        // Self-visibility: we read only our own cp.async copies -> no barrier.
        if (c == 0 || c == 1) asm volatile("cp.async.wait_group 2;\n" ::);
        else if (c == 2)      asm volatile("cp.async.wait_group 1;\n" ::);
        else                  asm volatile("cp.async.wait_group 0;\n" ::);

        float4 p[4];
#pragma unroll
        for (int i = 0; i < 4; ++i)
            p[i] = tile[(warp + i * 8) * 32 + lane];

        if (c + 3 < NCH) issue(c + 3);   // refill our own consumed slots (c==0)

        // Pos norms + per-warp column-sum partial.
#pragma unroll
        for (int i = 0; i < 4; ++i)
            pn[i] += dot4(p[i], p[i]);
        float4 spv;
        spv.x = (p[0].x + p[1].x) + (p[2].x + p[3].x);
        spv.y = (p[0].y + p[1].y) + (p[2].y + p[3].y);
        spv.z = (p[0].z + p[1].z) + (p[2].z + p[3].z);
        spv.w = (p[0].w + p[1].w) + (p[2].w + p[3].w);
        *(float4*)&spart[(sb * 8 + warp) * CHUNK + lane * 4] = spv;

        __syncthreads();   // the ONLY per-chunk barrier (colsum exchange)

        float4 sc = *(const float4*)&spart[(sb * 8 + 0) * CHUNK + lane * 4];
#pragma unroll
        for (int w = 1; w < 8; ++w) {
            float4 t = *(const float4*)&spart[(sb * 8 + w) * CHUNK + lane * 4];
            sc.x += t.x; sc.y += t.y; sc.z += t.z; sc.w += t.w;
        }
#pragma unroll
        for (int i = 0; i < 4; ++i) {
            tp[i] += dot4(p[i], sc);
            nn[i] += dot4(n[i], n[i]);
            tn[i] += dot4(n[i], sc);
        }
        // spart[sb] rewritten at chunk c+2, after barrier c+1 -> safe.
    }

    // ---- single end-of-CTA flush: publish this quarter's row partials ----
#pragma unroll
    for (int i = 0; i < 4; ++i) {
        const float a = wsum(pn[i]);
        const float b = wsum(tp[i]);
        const float d = wsum(nn[i]);
        const float e = wsum(tn[i]);
        if (lane == 0) {
            const int row = warp + i * 8;
            g_scratch[cls][part][0][row] = a;
            g_scratch[cls][part][1][row] = b;
            g_scratch[cls][part][2][row] = d;
            g_scratch[cls][part][3][row] = e;
        }
    }
    __syncthreads();       // all 32 scratch rows issued before the count

    if (warp != 0) return; // warps 1-7 exit; slot frees as warp0 finishes

    unsigned fin = 0;
    if (lane == 0) {
        __threadfence();                       // publish scratch
        const unsigned old = atomicAdd(&g_done[cls], 1u);
        fin = ((old & (NPART - 1u)) == (NPART - 1u)) ? 1u : 0u;
    }
    fin = __shfl_sync(0xffffffffu, fin, 0);
    if (!fin) return;

    // ---- per-class finisher (last-arriving quarter; fixed-order sums) ----
    __threadfence();
    float fpn = 0.f, ftp = 0.f, fnn = 0.f, ftn = 0.f;
#pragma unroll
    for (int s = 0; s < NPART; ++s) {
        fpn += __ldcg(&g_scratch[cls][s][0][lane]);
        ftp += __ldcg(&g_scratch[cls][s][1][lane]);
        fnn += __ldcg(&g_scratch[cls][s][2][lane]);
        ftn += __ldcg(&g_scratch[cls][s][3][lane]);
    }
    const float ssum  = wsum(ftp);                 // ||s||^2 = sum_i pos_i·s
    const float anorm = ssum * (1.0f / 1024.0f);   // ||s||^2 / 32^2
    const float ap2   = fpn - ftp * (1.0f / 16.0f) + anorm;
    const float nd2   = fnn - ftn * (1.0f / 16.0f) + anorm;

    float mn = nd2;
#pragma unroll
    for (int o = 16; o > 0; o >>= 1)
        mn = fminf(mn, __shfl_xor_sync(0xffffffffu, mn, o));
    const float an = sqrtf(fmaxf(mn, 0.f));

    float t = fmaxf(sqrtf(fmaxf(ap2, 0.f)) - an + MARGIN, 0.f);
    const float term = wsum(t * t);

    unsigned old2 = 0;
    if (lane == 0) {
        g_class_loss[cls] = term;
        __threadfence();
        old2 = atomicAdd(&g_cls_done, 1u);
    }
    old2 = __shfl_sync(0xffffffffu, old2, 0);
    if ((old2 & (NCLS - 1u)) != (NCLS - 1u)) return;

    // ---- global finisher: fixed-order mean over 256 class losses ----
    __threadfence();
    float v = 0.f;
#pragma unroll
    for (int q = 0; q < NCLS / 32; ++q)
        v += __ldcg(&g_class_loss[q * 32 + lane]);
    v = wsum(v);
    if (lane == 0) out[0] = v * (1.0f / (float)NCLS);
}

extern "C" void kernel_launch(void* const* d_in, const int* in_sizes, int n_in,
                              void* d_out, int out_size)
{
    (void)in_sizes; (void)n_in; (void)out_size;
    const float* emb = (const float*)d_in[0];   // [16384, 2048] fp32
    // d_in[1] (target) is unused by the reference computation.
    cudaFuncSetAttribute(ccl_kernel, cudaFuncAttributeMaxDynamicSharedMemorySize,
                         SMEM_BYTES);
    ccl_kernel<<<GRID, THREADS, SMEM_BYTES>>>(emb, (float*)d_out);
}

// round 13
// speedup vs baseline: 1.1659x; 1.1659x over previous
#include <cuda_runtime.h>

// CoupledClustersLossV2 — R10 schedule (best known) + neg-rows bypass SMEM.
// embeddings: [256 cls][2 pos/neg][32 samples][2048] fp32 = 128 MB.
// ||x - a||^2 = ||x||^2 - (x·s)/16 + ||s||^2/1024,  s = sum of 32 pos rows.
//
// Settled by R10-R12: 256 CTAs x 16 fully-static unrolled chunks is the
// right schedule (dynamic loops and short CTAs both regressed). Remaining
// limiter is SMEM crossbar traffic (~100KB/chunk/CTA ~ 14us/SM, co-binding
// with the 16us DRAM stream). Neg rows don't feed the column sum, so they
// now go GMEM->registers directly (__ldcg float4, perfectly coalesced in
// this layout), deleting 32KB/chunk of SMEM traffic and halving cp.async
// count. Neg LDGs issue BEFORE wait_group so DRAM latency hides under it.
// Everything else identical to the 29.4us kernel: self-visible cp.async
// (each thread copies exactly the slots it reads -> no tile barrier),
// 3 stages, ONE barrier/chunk (colsum exchange), single end-of-CTA flush,
// epoch-counter finishers (replay-safe), fixed-order sums (deterministic).

#define NCLS     256
#define NS       32
#define DIM      2048
#define CHUNK    128
#define THREADS  256
#define NCHUNKS  16                           // DIM / CHUNK, compile-time
#define NSTAGE   3
#define TILE_F4  1024                         // pos-only: 32 rows x 32 float4 = 16KB
#define SPART_F  (8 * CHUNK)
#define SMEM_BYTES (NSTAGE * TILE_F4 * 16 + 2 * SPART_F * 4)   // 53248
#define ROW_F4   (DIM / 4)                    // 512
#define MARGIN   0.3f

__device__ float        g_class_loss[NCLS];
__device__ unsigned int g_cls_done;           // epoch counter (never reset)

__device__ __forceinline__ float dot4(float4 a, float4 b) {
    return fmaf(a.x, b.x, fmaf(a.y, b.y, fmaf(a.z, b.z, a.w * b.w)));
}
__device__ __forceinline__ float wsum(float v) {
#pragma unroll
    for (int o = 16; o > 0; o >>= 1) v += __shfl_xor_sync(0xffffffffu, v, o);
    return v;
}
__device__ __forceinline__ void cp_async16(unsigned smem_dst, const float4* gsrc) {
    asm volatile("cp.async.cg.shared.global [%0], [%1], 16;\n"
                 :: "r"(smem_dst), "l"(gsrc));
}

__global__ __launch_bounds__(THREADS, 2)
void ccl_kernel(const float* __restrict__ emb, float* __restrict__ out)
{
    extern __shared__ float4 sh4[];                       // [NSTAGE][TILE_F4] pos tiles
    float* spart = (float*)(sh4 + NSTAGE * TILE_F4);      // [2][8][CHUNK]
    __shared__ float red[4][NS];                          // flush staging

    const int cls  = blockIdx.x;
    const int tid  = threadIdx.x;
    const int warp = tid >> 5;
    const int lane = tid & 31;

    // This thread's fixed slots: pos rows warp+8i (i=0..3), f4-column lane.
    const unsigned slot0  = (unsigned)((warp * 32 + lane) * 16);
    const unsigned smbase = (unsigned)__cvta_generic_to_shared(sh4);
    const float4*  gbase  = (const float4*)emb + ((size_t)cls << 15)   // 2*NS*DIM/4
                            + (size_t)warp * ROW_F4 + lane;

    // Issue pos chunk c (this thread's own 4 slots) + commit.
    auto issue = [&](int c) {
        const float4*  g  = gbase + (c << 5);             // c * CHUNK/4
        const unsigned sb = smbase + (unsigned)(c % NSTAGE) * (TILE_F4 * 16);
#pragma unroll
        for (int i = 0; i < 4; ++i)
            cp_async16(sb + slot0 + i * 4096u, g + (size_t)(i * 8) * ROW_F4);
        asm volatile("cp.async.commit_group;\n" ::);
    };

    issue(0); issue(1); issue(2);

    float pn[4] = {0.f,0.f,0.f,0.f};
    float tp[4] = {0.f,0.f,0.f,0.f};
    float nn[4] = {0.f,0.f,0.f,0.f};
    float tn[4] = {0.f,0.f,0.f,0.f};

#pragma unroll
    for (int c = 0; c < NCHUNKS; ++c) {
        const int sb = c & 1;
        const float4* tile = sh4 + (c % NSTAGE) * TILE_F4;

        // Neg rows straight from GMEM (coalesced: warp = 512B contiguous).
        // Issued BEFORE the wait so DRAM latency hides under it. .cg = no L1.
        float4 n[4];
#pragma unroll
        for (int i = 0; i < 4; ++i)
            n[i] = __ldcg(gbase + (c << 5) + (size_t)(NS + i * 8) * ROW_F4);

        // Self-visibility: we read only our own cp.async copies -> no barrier.
        if (c + 2 < NCHUNKS)      asm volatile("cp.async.wait_group 2;\n" ::);
        else if (c + 1 < NCHUNKS) asm volatile("cp.async.wait_group 1;\n" ::);
        else                      asm volatile("cp.async.wait_group 0;\n" ::);

        float4 p[4];
#pragma unroll
        for (int i = 0; i < 4; ++i)
            p[i] = tile[(warp + i * 8) * 32 + lane];

        // Pos norms + per-warp column-sum partial (consumes p from registers).
#pragma unroll
        for (int i = 0; i < 4; ++i)
            pn[i] += dot4(p[i], p[i]);
        float4 spv;
        spv.x = (p[0].x + p[1].x) + (p[2].x + p[3].x);
        spv.y = (p[0].y + p[1].y) + (p[2].y + p[3].y);
        spv.z = (p[0].z + p[1].z) + (p[2].z + p[3].z);
        spv.w = (p[0].w + p[1].w) + (p[2].w + p[3].w);
        *(float4*)&spart[(sb * 8 + warp) * CHUNK + lane * 4] = spv;

        __syncthreads();   // the ONLY per-chunk barrier (colsum exchange)

        // Refill this stage (our own already-consumed slots).
        if (c + 3 < NCHUNKS) issue(c + 3);

        float4 sc = *(const float4*)&spart[(sb * 8 + 0) * CHUNK + lane * 4];
#pragma unroll
        for (int w = 1; w < 8; ++w) {
            float4 t = *(const float4*)&spart[(sb * 8 + w) * CHUNK + lane * 4];
            sc.x += t.x; sc.y += t.y; sc.z += t.z; sc.w += t.w;
        }
#pragma unroll
        for (int i = 0; i < 4; ++i) {
            tp[i] += dot4(p[i], sc);
            nn[i] += dot4(n[i], n[i]);
            tn[i] += dot4(n[i], sc);
        }
        // spart[sb] rewritten at chunk c+2, after barrier c+1 -> safe.
    }

    // ---- single end-of-CTA flush: class loss computed entirely in-CTA ----
#pragma unroll
    for (int i = 0; i < 4; ++i) {
        const float a = wsum(pn[i]);
        const float b = wsum(tp[i]);
        const float d = wsum(nn[i]);
        const float e = wsum(tn[i]);
        if (lane == 0) {
            const int row = warp + i * 8;
            red[0][row] = a;
            red[1][row] = b;
            red[2][row] = d;
            red[3][row] = e;
        }
    }
    __syncthreads();

    if (warp == 0) {
        const float pnv = red[0][lane];
        const float tpv = red[1][lane];
        const float nnv = red[2][lane];
        const float tnv = red[3][lane];

        const float ssum  = wsum(tpv);                 // ||s||^2
        const float anorm = ssum * (1.0f / 1024.0f);   // ||s||^2 / 32^2
        const float ap2   = pnv - tpv * (1.0f / 16.0f) + anorm;
        const float nd2   = nnv - tnv * (1.0f / 16.0f) + anorm;

        float mn = nd2;
#pragma unroll
        for (int o = 16; o > 0; o >>= 1)
            mn = fminf(mn, __shfl_xor_sync(0xffffffffu, mn, o));
        const float an = sqrtf(fmaxf(mn, 0.f));

        float t = fmaxf(sqrtf(fmaxf(ap2, 0.f)) - an + MARGIN, 0.f);
        const float term = wsum(t * t);

        unsigned old = 0;
        if (lane == 0) {
            g_class_loss[cls] = term;
            __threadfence();
            old = atomicAdd(&g_cls_done, 1u);
        }
        old = __shfl_sync(0xffffffffu, old, 0);
        if ((old & (NCLS - 1u)) == (NCLS - 1u)) {
            // ---- global finisher: fixed-order mean over 256 class losses ----
            __threadfence();
            float v = 0.f;
#pragma unroll
            for (int q = 0; q < NCLS / 32; ++q)
                v += __ldcg(&g_class_loss[q * 32 + lane]);
            v = wsum(v);
            if (lane == 0) out[0] = v * (1.0f / (float)NCLS);
        }
    }
}

extern "C" void kernel_launch(void* const* d_in, const int* in_sizes, int n_in,
                              void* d_out, int out_size)
{
    (void)in_sizes; (void)n_in; (void)out_size;
    const float* emb = (const float*)d_in[0];   // [16384, 2048] fp32
    // d_in[1] (target) is unused by the reference computation.
    cudaFuncSetAttribute(ccl_kernel, cudaFuncAttributeMaxDynamicSharedMemorySize,
                         SMEM_BYTES);
    ccl_kernel<<<NCLS, THREADS, SMEM_BYTES>>>(emb, (float*)d_out);
}